// round 5
// baseline (speedup 1.0000x reference)
#include <cuda_runtime.h>
#include <cstddef>
#include <cstdint>

#define NB   4
#define TSZ  16
#define SRr  4
#define PD   1
#define SSn  11     // search span = 2*(SR+PADD)+1
#define SSC  9      // cropped span = 2*SR+1
#define WINs 26     // T + 2*(SR+PADD)
#define SWt  0.1f

// ---------------- scratch (device globals; no allocation) ----------------
__device__ float g_ps1[NB*256*256], g_pd1[NB*256*256];
__device__ float g_ps2[NB*128*128], g_pd2[NB*128*128];
__device__ float g_ps3[NB*64*64],   g_pd3[NB*64*64];
__device__ float g_offA[NB*16*16*2];
__device__ float g_offB[NB*16*16*2];

// =========================================================================
// Fused pyramid: one block = one 8x8 tile of level-3 for one image.
// Fused blur(5x5,zero-pad)+avgpool(2) == 6-tap separable: w(u,v)=ww[u]*ww[v]
// =========================================================================
__global__ void __launch_bounds__(256, 4)
pyr_kernel(const float* __restrict__ src, const float* __restrict__ dst,
           float* __restrict__ ps1, float* __restrict__ pd1,
           float* __restrict__ ps2, float* __restrict__ pd2,
           float* __restrict__ ps3, float* __restrict__ pd3)
{
    __shared__ float s_a[92*45];   // tmp (horizontal pass results)
    __shared__ float s_b[44*45];   // level buffers

    const int b  = blockIdx.x;
    const int im = b >> 6;                 // 0..7 (0-3 src, 4-7 dst)
    const int t  = b & 63;
    const int bi = t >> 3, bj = t & 7;
    const int tid = threadIdx.x;

    const float* in = (im < NB) ? (src + (size_t)im * 512 * 512)
                                : (dst + (size_t)(im - NB) * 512 * 512);
    float* o1 = (im < NB) ? (ps1 + (size_t)im * 256 * 256) : (pd1 + (size_t)(im-NB) * 256 * 256);
    float* o2 = (im < NB) ? (ps2 + (size_t)im * 128 * 128) : (pd2 + (size_t)(im-NB) * 128 * 128);
    float* o3 = (im < NB) ? (ps3 + (size_t)im *  64 *  64) : (pd3 + (size_t)(im-NB) *  64 *  64);

    // separable taps
    const float g0 = expf(-2.0f), g1 = expf(-0.5f), g2 = 1.0f;
    const float S  = g2 + 2.f*g1 + 2.f*g0;
    float ww[6];
    {
        const float ga[5] = {g0, g1, g2, g1, g0};
        ww[0] = 0.5f * ga[0] / S;
        #pragma unroll
        for (int u = 1; u < 5; u++) ww[u] = 0.5f * (ga[u] + ga[u-1]) / S;
        ww[5] = 0.5f * ga[4] / S;
    }

    const int yb = 64*bi - 14;
    const int xb = 64*bj - 14;

    // ---- pass 1h: horizontal on input -> tmp (92 rows x 44 cols)
    for (int id = tid; id < 92*44; id += 256) {
        int yy = id / 44, cx = id - yy*44;
        int gy = yb + yy;
        float v = 0.f;
        if (gy >= 0 && gy < 512) {
            const float* row = in + (size_t)gy * 512;
            int gx = xb + 2*cx;
            #pragma unroll
            for (int k = 0; k < 6; k++) {
                int xx = gx + k;
                if (xx >= 0 && xx < 512) v = fmaf(ww[k], row[xx], v);
            }
        }
        s_a[yy*45 + cx] = v;
    }
    __syncthreads();

    // ---- pass 1v: -> level1 (44x44), write owned 32x32
    for (int id = tid; id < 44*44; id += 256) {
        int cy = id / 44, cx = id - cy*44;
        float v = 0.f;
        #pragma unroll
        for (int k = 0; k < 6; k++) v = fmaf(ww[k], s_a[(2*cy + k)*45 + cx], v);
        int r1 = 32*bi - 6 + cy, c1 = 32*bj - 6 + cx;
        bool inimg = (r1 >= 0 && r1 < 256 && c1 >= 0 && c1 < 256);
        s_b[cy*45 + cx] = inimg ? v : 0.f;
        if (cy >= 6 && cy < 38 && cx >= 6 && cx < 38)
            o1[(size_t)r1 * 256 + c1] = v;
    }
    __syncthreads();

    // ---- pass 2h
    for (int id = tid; id < 44*20; id += 256) {
        int yy = id / 20, cx = id - yy*20;
        float v = 0.f;
        #pragma unroll
        for (int k = 0; k < 6; k++) v = fmaf(ww[k], s_b[yy*45 + 2*cx + k], v);
        s_a[yy*21 + cx] = v;
    }
    __syncthreads();

    // ---- pass 2v: -> level2 (20x20), write owned 16x16
    for (int id = tid; id < 20*20; id += 256) {
        int cy = id / 20, cx = id - cy*20;
        float v = 0.f;
        #pragma unroll
        for (int k = 0; k < 6; k++) v = fmaf(ww[k], s_a[(2*cy + k)*21 + cx], v);
        int r2 = 16*bi - 2 + cy, c2 = 16*bj - 2 + cx;
        bool inimg = (r2 >= 0 && r2 < 128 && c2 >= 0 && c2 < 128);
        s_b[cy*21 + cx] = inimg ? v : 0.f;
        if (cy >= 2 && cy < 18 && cx >= 2 && cx < 18)
            o2[(size_t)r2 * 128 + c2] = v;
    }
    __syncthreads();

    // ---- pass 3h
    for (int id = tid; id < 20*8; id += 256) {
        int yy = id >> 3, cx = id & 7;
        float v = 0.f;
        #pragma unroll
        for (int k = 0; k < 6; k++) v = fmaf(ww[k], s_b[yy*21 + 2*cx + k], v);
        s_a[yy*9 + cx] = v;
    }
    __syncthreads();

    // ---- pass 3v: -> level3 (8x8)
    for (int id = tid; id < 64; id += 256) {
        int cy = id >> 3, cx = id & 7;
        float v = 0.f;
        #pragma unroll
        for (int k = 0; k < 6; k++) v = fmaf(ww[k], s_a[(2*cy + k)*9 + cx], v);
        o3[(size_t)(8*bi + cy) * 64 + (8*bj + cx)] = v;
    }
}

// =========================================================================
// One alignment level: block = one tile.
// MSE: thread (sy,i) holds full window row [26] + src row [16] in regs,
// fully unrolled sx -> static register indexing, zero shift MOVs.
// =========================================================================
__global__ void __launch_bounds__(256, 4)
step_kernel(const float* __restrict__ src, const float* __restrict__ dst,
            int H, int nth,
            const float* __restrict__ prev_off, int pnth,
            float* __restrict__ out_off,     // per-tile (non-final), else null
            float* __restrict__ out_pix)     // final pixel maps (d_out), else null
{
    const int W = H, ntw = nth, pntw = pnth;
    int tile = blockIdx.x;
    int tx = tile % ntw;
    int t2 = tile / ntw;
    int ty = t2 % nth;
    int nb = t2 / nth;
    int tid = threadIdx.x;

    __shared__ float s_src[TSZ*TSZ];
    __shared__ float s_win[WINs*(WINs+1)];
    __shared__ float s_part[SSn*SSn*17];     // [cand][i], pad 17
    __shared__ float s_dist[SSn*SSn];
    __shared__ unsigned long long s_red[3];
    __shared__ float s_res[3];

    // ---- inherit init offset (all threads; same-address LDG broadcasts)
    float iyf = 0.f, ixf = 0.f;
    if (prev_off) {
        const float* p = prev_off + ((size_t)((nb*pnth + (ty>>1))*pntw + (tx>>1)))*2;
        float iy = (float)(ty*TSZ), ix = (float)(tx*TSZ);
        iyf = rintf(fminf(fmaxf(2.f*p[0] + iy, 0.f), (float)(H-TSZ)) - iy);
        ixf = rintf(fminf(fmaxf(2.f*p[1] + ix, 0.f), (float)(W-TSZ)) - ix);
    }
    const int oy = (int)iyf;
    const int ox = (int)ixf;

    const float* simg = src + (size_t)nb * H * W;
    const float* dimg = dst + (size_t)nb * H * W;

    // ---- load src tile (16x16, one elem/thread)
    {
        int i = tid >> 4, j = tid & 15;
        s_src[tid] = simg[(size_t)(ty*TSZ + i) * W + tx*TSZ + j];
    }

    // ---- load 26x26 dst window with clamped gather
    int y0 = ty*TSZ + oy - (SRr + PD);
    int x0 = tx*TSZ + ox - (SRr + PD);
    for (int idx = tid; idx < WINs*WINs; idx += 256) {
        int r = idx / WINs, c = idx - r*WINs;
        int yy = min(max(y0 + r, 0), H - 1);
        int xx = min(max(x0 + c, 0), W - 1);
        s_win[r*(WINs+1) + c] = dimg[(size_t)yy * W + xx];
    }
    __syncthreads();

    // ---- MSE partials: 176 threads = 11 sy x 16 rows; w[26] in registers
    if (tid < SSn*TSZ) {
        const int sy = tid >> 4, i = tid & 15;
        float s[16], w[WINs];
        #pragma unroll
        for (int j = 0; j < 16; j++) s[j] = s_src[i*TSZ + j];
        const float* wr = s_win + (sy + i)*(WINs+1);
        #pragma unroll
        for (int j = 0; j < WINs; j++) w[j] = wr[j];
        float* pp = s_part + sy*SSn*17 + i;
        #pragma unroll
        for (int sx = 0; sx < SSn; sx++) {
            float a0 = 0.f, a1 = 0.f;
            #pragma unroll
            for (int j = 0; j < 16; j += 2) {
                float d0 = w[sx + j]     - s[j];     a0 = fmaf(d0, d0, a0);
                float d1 = w[sx + j + 1] - s[j + 1]; a1 = fmaf(d1, d1, a1);
            }
            pp[sx*17] = a0 + a1;
        }
    }
    __syncthreads();

    // ---- reduce over rows + spatial penalty
    if (tid < SSn*SSn) {
        const float* p = s_part + tid*17;
        float q0 = (p[0] + p[1])   + (p[2] + p[3]);
        float q1 = (p[4] + p[5])   + (p[6] + p[7]);
        float q2 = (p[8] + p[9])   + (p[10] + p[11]);
        float q3 = (p[12] + p[13]) + (p[14] + p[15]);
        float sum = (q0 + q1) + (q2 + q3);
        int sy = tid / SSn, sx = tid - (tid/SSn)*SSn;
        float ay = ((float)sy - (float)(SRr+PD)) / (float)SSn;
        float ax = ((float)sx - (float)(SRr+PD)) / (float)SSn;
        s_dist[tid] = sum * (1.0f/256.0f) + SWt * (ay*ay + ax*ax);
    }
    __syncthreads();

    // ---- parallel argmin over 81 cropped candidates (first-index tie-break)
    {
        unsigned long long key = ~0ULL;
        if (tid < SSC*SSC) {
            int py = tid / SSC, px = tid - (tid/SSC)*SSC;
            float v = s_dist[(py+PD)*SSn + px + PD];
            key = ((unsigned long long)__float_as_uint(v) << 32) | (unsigned)tid;
        }
        if (tid < 96) {
            #pragma unroll
            for (int o = 16; o > 0; o >>= 1) {
                unsigned long long other = __shfl_down_sync(0xffffffffu, key, o);
                key = min(key, other);
            }
            if ((tid & 31) == 0) s_red[tid >> 5] = key;
        }
    }
    __syncthreads();

    // ---- subpixel refine (one thread)
    if (tid == 0) {
        unsigned long long key = min(min(s_red[0], s_red[1]), s_red[2]);
        int bk = (int)(key & 0xffffffffu);
        float best = __uint_as_float((unsigned)(key >> 32));
        int py = bk / SSC, px = bk - (bk/SSC)*SSC;
        float r[9];
        #pragma unroll
        for (int dy = 0; dy < 3; dy++)
            #pragma unroll
            for (int dx = 0; dx < 3; dx++)
                r[dy*3+dx] = s_dist[(py+PD-1+dy)*SSn + (px+PD-1+dx)];

        float a11 = (  r[0]-2.f*r[1]+r[2] + 2.f*r[3]-4.f*r[4]+2.f*r[5] +   r[6]-2.f*r[7]+r[8]) * 0.25f;
        float a22 = (  r[0]+2.f*r[1]+r[2] - 2.f*r[3]-4.f*r[4]-2.f*r[5] +   r[6]+2.f*r[7]+r[8]) * 0.25f;
        float a12 = (  r[0]        -r[2]                               -   r[6]         +r[8]) * 0.25f;
        float b1  = ( -r[0]        +r[2] - 2.f*r[3]        +2.f*r[5]   -   r[6]         +r[8]) * 0.125f;
        float b2  = ( -r[0]-2.f*r[1]-r[2]                              +   r[6]+2.f*r[7]+r[8]) * 0.125f;
        a11 = fmaxf(a11, 0.f);
        a22 = fmaxf(a22, 0.f);
        float det  = a11*a22 - a12*a12;
        float a12z = (det < 0.f) ? 0.f : a12;
        float mux  = -(a22*b1 - a12z*b2) / det;
        float muy  = -(a11*b2 - a12z*b1) / det;
        float mlen = sqrtf(muy*muy + mux*mux);
        float dxs  = (mlen < 1.f) ? mux : 0.f;   // NaN/Inf -> 0, matches jnp.where
        float dys  = (mlen < 1.f) ? muy : 0.f;

        float offy = iyf + (float)(py - SRr) + dys;
        float offx = ixf + (float)(px - SRr) + dxs;
        if (out_off) { out_off[(size_t)tile*2 + 0] = offy; out_off[(size_t)tile*2 + 1] = offx; }
        s_res[0] = offy; s_res[1] = offx; s_res[2] = best;
    }
    __syncthreads();

    // ---- final level: replicate tile result to pixel maps (coalesced f2)
    if (out_pix) {
        float2 ov = make_float2(s_res[0], s_res[1]);
        int i = tid >> 4, j = tid & 15;
        int y = ty*TSZ + i, x = tx*TSZ + j;
        size_t pix = ((size_t)nb * H + y) * W + x;
        reinterpret_cast<float2*>(out_pix)[pix] = ov;
        out_pix[(size_t)NB * H * W * 2 + pix] = s_res[2];
    }
}

// ---------------- launch ---------------------------------------------------
extern "C" void kernel_launch(void* const* d_in, const int* in_sizes, int n_in,
                              void* d_out, int out_size)
{
    const float* src = (const float*)d_in[0];
    const float* dst = (const float*)d_in[1];
    float* out = (float*)d_out;

    float *ps1, *pd1, *ps2, *pd2, *ps3, *pd3, *offA, *offB;
    cudaGetSymbolAddress((void**)&ps1,  g_ps1);
    cudaGetSymbolAddress((void**)&pd1,  g_pd1);
    cudaGetSymbolAddress((void**)&ps2,  g_ps2);
    cudaGetSymbolAddress((void**)&pd2,  g_pd2);
    cudaGetSymbolAddress((void**)&ps3,  g_ps3);
    cudaGetSymbolAddress((void**)&pd3,  g_pd3);
    cudaGetSymbolAddress((void**)&offA, g_offA);
    cudaGetSymbolAddress((void**)&offB, g_offB);

    // fused 3-level pyramid, src+dst together: 8 images x 64 tile-blocks
    pyr_kernel<<<8*64, 256>>>(src, dst, ps1, pd1, ps2, pd2, ps3, pd3);

    // coarse -> fine alignment
    step_kernel<<<NB*4*4,   256>>>(ps3, pd3,  64,  4, nullptr, 0,  offA, nullptr);
    step_kernel<<<NB*8*8,   256>>>(ps2, pd2, 128,  8, offA,    4,  offB, nullptr);
    step_kernel<<<NB*16*16, 256>>>(ps1, pd1, 256, 16, offB,    8,  offA, nullptr);
    step_kernel<<<NB*32*32, 256>>>(src, dst, 512, 32, offA,   16,  nullptr, out);
}

// round 7
// speedup vs baseline: 1.0367x; 1.0367x over previous
#include <cuda_runtime.h>
#include <cstddef>
#include <cstdint>

#define NB   4
#define TSZ  16
#define SRr  4
#define PD   1
#define SSn  11     // search span = 2*(SR+PADD)+1
#define SSC  9      // cropped span = 2*SR+1
#define WINs 26     // T + 2*(SR+PADD)
#define SWt  0.1f

// ---------------- scratch (device globals; no allocation) ----------------
__device__ float g_ps1[NB*256*256], g_pd1[NB*256*256];
__device__ float g_ps2[NB*128*128], g_pd2[NB*128*128];
__device__ float g_ps3[NB*64*64],   g_pd3[NB*64*64];
__device__ float g_offA[NB*16*16*2];
__device__ float g_offB[NB*16*16*2];

// grid barrier state (sense-reversal; returns to {0,0} after an even number
// of barriers per launch -> replay-deterministic)
__device__ unsigned g_bar_count = 0;
__device__ unsigned g_bar_sense = 0;

// ---------------- shared-memory union -------------------------------------
struct StepSh {
    float s_src[TSZ*TSZ];
    float s_win[WINs*(WINs+1)];
    float s_part[SSn*SSn*17];
    float s_dist[SSn*SSn];
    unsigned long long s_red[3];
    float s_res[3];
};
struct PyrSh {
    float a[92*45];
    float b[44*45];
};
union ShMem {
    StepSh st;
    PyrSh  py;
};

// ---------------- grid barrier (all blocks co-resident) --------------------
__device__ __forceinline__ void grid_barrier(int G, unsigned& local_sense)
{
    __syncthreads();
    if (threadIdx.x == 0) {
        local_sense ^= 1u;
        __threadfence();
        unsigned v = atomicAdd(&g_bar_count, 1u);
        if (v == (unsigned)(G - 1)) {
            g_bar_count = 0;
            __threadfence();
            *(volatile unsigned*)&g_bar_sense = local_sense;
        } else {
            while (*(volatile unsigned*)&g_bar_sense != local_sense)
                __nanosleep(64);
            __threadfence();
        }
    }
    __syncthreads();
}

// ---------------- pyramid work item: one 8x8 L3 tile of one image ----------
__device__ void pyr_block(PyrSh& sh, int vb,
                          const float* __restrict__ src, const float* __restrict__ dst,
                          float* __restrict__ ps1, float* __restrict__ pd1,
                          float* __restrict__ ps2, float* __restrict__ pd2,
                          float* __restrict__ ps3, float* __restrict__ pd3)
{
    const int im = vb >> 6;                 // 0..7 (0-3 src, 4-7 dst)
    const int t  = vb & 63;
    const int bi = t >> 3, bj = t & 7;
    const int tid = threadIdx.x;

    const float* in = (im < NB) ? (src + (size_t)im * 512 * 512)
                                : (dst + (size_t)(im - NB) * 512 * 512);
    float* o1 = (im < NB) ? (ps1 + (size_t)im * 256 * 256) : (pd1 + (size_t)(im-NB) * 256 * 256);
    float* o2 = (im < NB) ? (ps2 + (size_t)im * 128 * 128) : (pd2 + (size_t)(im-NB) * 128 * 128);
    float* o3 = (im < NB) ? (ps3 + (size_t)im *  64 *  64) : (pd3 + (size_t)(im-NB) *  64 *  64);

    // separable taps: fused blur(5x5,zero-pad)+avgpool(2) = 6-tap outer product
    const float g0 = expf(-2.0f), g1 = expf(-0.5f), g2 = 1.0f;
    const float S  = g2 + 2.f*g1 + 2.f*g0;
    float ww[6];
    {
        const float ga[5] = {g0, g1, g2, g1, g0};
        ww[0] = 0.5f * ga[0] / S;
        #pragma unroll
        for (int u = 1; u < 5; u++) ww[u] = 0.5f * (ga[u] + ga[u-1]) / S;
        ww[5] = 0.5f * ga[4] / S;
    }

    const int yb = 64*bi - 14;
    const int xb = 64*bj - 14;

    // pass 1h: input -> tmp (92 x 44)
    for (int id = tid; id < 92*44; id += 256) {
        int yy = id / 44, cx = id - yy*44;
        int gy = yb + yy;
        float v = 0.f;
        if (gy >= 0 && gy < 512) {
            const float* row = in + (size_t)gy * 512;
            int gx = xb + 2*cx;
            #pragma unroll
            for (int k = 0; k < 6; k++) {
                int xx = gx + k;
                if (xx >= 0 && xx < 512) v = fmaf(ww[k], row[xx], v);
            }
        }
        sh.a[yy*45 + cx] = v;
    }
    __syncthreads();

    // pass 1v: -> level1 (44x44), write owned 32x32
    for (int id = tid; id < 44*44; id += 256) {
        int cy = id / 44, cx = id - cy*44;
        float v = 0.f;
        #pragma unroll
        for (int k = 0; k < 6; k++) v = fmaf(ww[k], sh.a[(2*cy + k)*45 + cx], v);
        int r1 = 32*bi - 6 + cy, c1 = 32*bj - 6 + cx;
        bool inimg = (r1 >= 0 && r1 < 256 && c1 >= 0 && c1 < 256);
        sh.b[cy*45 + cx] = inimg ? v : 0.f;
        if (cy >= 6 && cy < 38 && cx >= 6 && cx < 38)
            o1[(size_t)r1 * 256 + c1] = v;
    }
    __syncthreads();

    // pass 2h
    for (int id = tid; id < 44*20; id += 256) {
        int yy = id / 20, cx = id - yy*20;
        float v = 0.f;
        #pragma unroll
        for (int k = 0; k < 6; k++) v = fmaf(ww[k], sh.b[yy*45 + 2*cx + k], v);
        sh.a[yy*21 + cx] = v;
    }
    __syncthreads();

    // pass 2v: -> level2 (20x20), write owned 16x16
    for (int id = tid; id < 20*20; id += 256) {
        int cy = id / 20, cx = id - cy*20;
        float v = 0.f;
        #pragma unroll
        for (int k = 0; k < 6; k++) v = fmaf(ww[k], sh.a[(2*cy + k)*21 + cx], v);
        int r2 = 16*bi - 2 + cy, c2 = 16*bj - 2 + cx;
        bool inimg = (r2 >= 0 && r2 < 128 && c2 >= 0 && c2 < 128);
        sh.b[cy*21 + cx] = inimg ? v : 0.f;
        if (cy >= 2 && cy < 18 && cx >= 2 && cx < 18)
            o2[(size_t)r2 * 128 + c2] = v;
    }
    __syncthreads();

    // pass 3h
    for (int id = tid; id < 20*8; id += 256) {
        int yy = id >> 3, cx = id & 7;
        float v = 0.f;
        #pragma unroll
        for (int k = 0; k < 6; k++) v = fmaf(ww[k], sh.b[yy*21 + 2*cx + k], v);
        sh.a[yy*9 + cx] = v;
    }
    __syncthreads();

    // pass 3v: -> level3 (8x8)
    for (int id = tid; id < 64; id += 256) {
        int cy = id >> 3, cx = id & 7;
        float v = 0.f;
        #pragma unroll
        for (int k = 0; k < 6; k++) v = fmaf(ww[k], sh.a[(2*cy + k)*9 + cx], v);
        o3[(size_t)(8*bi + cy) * 64 + (8*bj + cx)] = v;
    }
    __syncthreads();   // protect shared reuse across loop iterations
}

// ---------------- one alignment tile ---------------------------------------
__device__ void step_tile(StepSh& sh, int tile,
                          const float* __restrict__ src, const float* __restrict__ dst,
                          int H, int nth,
                          const float* __restrict__ prev_off, int pnth,
                          float* __restrict__ out_off, float* __restrict__ out_pix)
{
    const int W = H, ntw = nth, pntw = pnth;
    int tx = tile % ntw;
    int t2 = tile / ntw;
    int ty = t2 % nth;
    int nb = t2 / nth;
    int tid = threadIdx.x;

    // inherit init offset (all threads; same-address LDG broadcasts)
    float iyf = 0.f, ixf = 0.f;
    if (prev_off) {
        const float* p = prev_off + ((size_t)((nb*pnth + (ty>>1))*pntw + (tx>>1)))*2;
        float iy = (float)(ty*TSZ), ix = (float)(tx*TSZ);
        iyf = rintf(fminf(fmaxf(2.f*p[0] + iy, 0.f), (float)(H-TSZ)) - iy);
        ixf = rintf(fminf(fmaxf(2.f*p[1] + ix, 0.f), (float)(W-TSZ)) - ix);
    }
    const int oy = (int)iyf;
    const int ox = (int)ixf;

    const float* simg = src + (size_t)nb * H * W;
    const float* dimg = dst + (size_t)nb * H * W;

    // load src tile
    {
        int i = tid >> 4, j = tid & 15;
        sh.s_src[tid] = simg[(size_t)(ty*TSZ + i) * W + tx*TSZ + j];
    }

    // load 26x26 dst window (fast path when fully interior)
    int y0 = ty*TSZ + oy - (SRr + PD);
    int x0 = tx*TSZ + ox - (SRr + PD);
    if (y0 >= 0 && x0 >= 0 && y0 + WINs <= H && x0 + WINs <= W) {
        const float* base = dimg + (size_t)y0 * W + x0;
        for (int idx = tid; idx < WINs*WINs; idx += 256) {
            int r = idx / WINs, c = idx - r*WINs;
            sh.s_win[r*(WINs+1) + c] = base[(size_t)r * W + c];
        }
    } else {
        for (int idx = tid; idx < WINs*WINs; idx += 256) {
            int r = idx / WINs, c = idx - r*WINs;
            int yy = min(max(y0 + r, 0), H - 1);
            int xx = min(max(x0 + c, 0), W - 1);
            sh.s_win[r*(WINs+1) + c] = dimg[(size_t)yy * W + xx];
        }
    }
    __syncthreads();

    // MSE partials: 176 threads = 11 sy x 16 rows; window row in registers
    if (tid < SSn*TSZ) {
        const int sy = tid >> 4, i = tid & 15;
        float s[16], w[WINs];
        #pragma unroll
        for (int j = 0; j < 16; j++) s[j] = sh.s_src[i*TSZ + j];
        const float* wr = sh.s_win + (sy + i)*(WINs+1);
        #pragma unroll
        for (int j = 0; j < WINs; j++) w[j] = wr[j];
        float* pp = sh.s_part + sy*SSn*17 + i;
        #pragma unroll
        for (int sx = 0; sx < SSn; sx++) {
            float a0 = 0.f, a1 = 0.f;
            #pragma unroll
            for (int j = 0; j < 16; j += 2) {
                float d0 = w[sx + j]     - s[j];     a0 = fmaf(d0, d0, a0);
                float d1 = w[sx + j + 1] - s[j + 1]; a1 = fmaf(d1, d1, a1);
            }
            pp[sx*17] = a0 + a1;
        }
    }
    __syncthreads();

    // reduce over rows + spatial penalty
    if (tid < SSn*SSn) {
        const float* p = sh.s_part + tid*17;
        float q0 = (p[0] + p[1])   + (p[2] + p[3]);
        float q1 = (p[4] + p[5])   + (p[6] + p[7]);
        float q2 = (p[8] + p[9])   + (p[10] + p[11]);
        float q3 = (p[12] + p[13]) + (p[14] + p[15]);
        float sum = (q0 + q1) + (q2 + q3);
        int sy = tid / SSn, sx = tid - (tid/SSn)*SSn;
        float ay = ((float)sy - (float)(SRr+PD)) / (float)SSn;
        float ax = ((float)sx - (float)(SRr+PD)) / (float)SSn;
        sh.s_dist[tid] = sum * (1.0f/256.0f) + SWt * (ay*ay + ax*ax);
    }
    __syncthreads();

    // parallel argmin over 81 cropped candidates (first-index tie-break)
    {
        unsigned long long key = ~0ULL;
        if (tid < SSC*SSC) {
            int py = tid / SSC, px = tid - (tid/SSC)*SSC;
            float v = sh.s_dist[(py+PD)*SSn + px + PD];
            key = ((unsigned long long)__float_as_uint(v) << 32) | (unsigned)tid;
        }
        if (tid < 96) {
            #pragma unroll
            for (int o = 16; o > 0; o >>= 1) {
                unsigned long long other = __shfl_down_sync(0xffffffffu, key, o);
                key = min(key, other);
            }
            if ((tid & 31) == 0) sh.s_red[tid >> 5] = key;
        }
    }
    __syncthreads();

    // subpixel refine (one thread)
    if (tid == 0) {
        unsigned long long key = min(min(sh.s_red[0], sh.s_red[1]), sh.s_red[2]);
        int bk = (int)(key & 0xffffffffu);
        float best = __uint_as_float((unsigned)(key >> 32));
        int py = bk / SSC, px = bk - (bk/SSC)*SSC;
        float r[9];
        #pragma unroll
        for (int dy = 0; dy < 3; dy++)
            #pragma unroll
            for (int dx = 0; dx < 3; dx++)
                r[dy*3+dx] = sh.s_dist[(py+PD-1+dy)*SSn + (px+PD-1+dx)];

        float a11 = (  r[0]-2.f*r[1]+r[2] + 2.f*r[3]-4.f*r[4]+2.f*r[5] +   r[6]-2.f*r[7]+r[8]) * 0.25f;
        float a22 = (  r[0]+2.f*r[1]+r[2] - 2.f*r[3]-4.f*r[4]-2.f*r[5] +   r[6]+2.f*r[7]+r[8]) * 0.25f;
        float a12 = (  r[0]        -r[2]                               -   r[6]         +r[8]) * 0.25f;
        float b1  = ( -r[0]        +r[2] - 2.f*r[3]        +2.f*r[5]   -   r[6]         +r[8]) * 0.125f;
        float b2  = ( -r[0]-2.f*r[1]-r[2]                              +   r[6]+2.f*r[7]+r[8]) * 0.125f;
        a11 = fmaxf(a11, 0.f);
        a22 = fmaxf(a22, 0.f);
        float det  = a11*a22 - a12*a12;
        float a12z = (det < 0.f) ? 0.f : a12;
        float mux  = -(a22*b1 - a12z*b2) / det;
        float muy  = -(a11*b2 - a12z*b1) / det;
        float mlen = sqrtf(muy*muy + mux*mux);
        float dxs  = (mlen < 1.f) ? mux : 0.f;
        float dys  = (mlen < 1.f) ? muy : 0.f;

        float offy = iyf + (float)(py - SRr) + dys;
        float offx = ixf + (float)(px - SRr) + dxs;
        if (out_off) { out_off[(size_t)tile*2 + 0] = offy; out_off[(size_t)tile*2 + 1] = offx; }
        sh.s_res[0] = offy; sh.s_res[1] = offx; sh.s_res[2] = best;
    }
    __syncthreads();

    // final level: replicate tile result to pixel maps (coalesced f2)
    if (out_pix) {
        float2 ov = make_float2(sh.s_res[0], sh.s_res[1]);
        int i = tid >> 4, j = tid & 15;
        int y = ty*TSZ + i, x = tx*TSZ + j;
        size_t pix = ((size_t)nb * H + y) * W + x;
        reinterpret_cast<float2*>(out_pix)[pix] = ov;
        out_pix[(size_t)NB * H * W * 2 + pix] = sh.s_res[2];
    }
    __syncthreads();   // protect shared reuse across loop iterations
}

// ---------------- persistent mega-kernel ------------------------------------
__global__ void __launch_bounds__(256)
align_kernel(const float* __restrict__ src, const float* __restrict__ dst,
             float* __restrict__ out, int G)
{
    __shared__ ShMem sh;
    unsigned local_sense = 0;

    // phase P: pyramid (512 work items)
    for (int vb = blockIdx.x; vb < 8*64; vb += G)
        pyr_block(sh.py, vb, src, dst, g_ps1, g_pd1, g_ps2, g_pd2, g_ps3, g_pd3);
    grid_barrier(G, local_sense);

    // level 3 (coarsest): 64 tiles
    for (int t = blockIdx.x; t < NB*4*4; t += G)
        step_tile(sh.st, t, g_ps3, g_pd3,  64,  4, nullptr, 0,  g_offA, nullptr);
    grid_barrier(G, local_sense);

    // level 2: 256 tiles
    for (int t = blockIdx.x; t < NB*8*8; t += G)
        step_tile(sh.st, t, g_ps2, g_pd2, 128,  8, g_offA,  4,  g_offB, nullptr);
    grid_barrier(G, local_sense);

    // level 1: 1024 tiles
    for (int t = blockIdx.x; t < NB*16*16; t += G)
        step_tile(sh.st, t, g_ps1, g_pd1, 256, 16, g_offB,  8,  g_offA, nullptr);
    grid_barrier(G, local_sense);

    // level 0 (finest): 4096 tiles, writes pixel maps
    for (int t = blockIdx.x; t < NB*32*32; t += G)
        step_tile(sh.st, t, src, dst, 512, 32, g_offA, 16,  nullptr, out);
}

// ---------------- launch ---------------------------------------------------
extern "C" void kernel_launch(void* const* d_in, const int* in_sizes, int n_in,
                              void* d_out, int out_size)
{
    const float* src = (const float*)d_in[0];
    const float* dst = (const float*)d_in[1];
    float* out = (float*)d_out;

    static int G = 0;
    if (G == 0) {
        int nsm = 0, bpm = 0;
        cudaDeviceGetAttribute(&nsm, cudaDevAttrMultiProcessorCount, 0);
        cudaOccupancyMaxActiveBlocksPerMultiprocessor(&bpm, align_kernel, 256, sizeof(ShMem));
        if (bpm < 1) bpm = 1;
        G = nsm * bpm;
    }

    align_kernel<<<G, 256>>>(src, dst, out, G);
}